// round 9
// baseline (speedup 1.0000x reference)
#include <cuda_runtime.h>
#include <cuda_bf16.h>
#include <float.h>
#include <stdint.h>

#define N_BINS 25
#define BLOCK_THREADS 128
#define WARPS_PER_BLOCK 4
#define BLOCKS_PER_SM 16
#define GRID_BLOCKS (148 * BLOCKS_PER_SM)      // 2368
#define ROW_F4 25                              // float4 per row
#define TILE_ROWS 4                            // rows per warp tile
#define TILE_F4 (TILE_ROWS * ROW_F4)           // 100 float4 = 1.6 KB
#define BUF_F4 (2 * TILE_F4)                   // double buffer = 3.2 KB / warp

__device__ float    g_accum[75];     // [0..24]=cnt [25..49]=conf [50..74]=acc
__device__ unsigned g_done;

__device__ __forceinline__ void cp_async16(uint32_t dst, const float4* src) {
    asm volatile("cp.async.cg.shared.global [%0], [%1], 16;\n" :: "r"(dst), "l"(src));
}
__device__ __forceinline__ void cp_commit() {
    asm volatile("cp.async.commit_group;\n" ::: "memory");
}
template <int N>
__device__ __forceinline__ void cp_wait() {
    asm volatile("cp.async.wait_group %0;\n" :: "n"(N) : "memory");
}

// Stage one 4-row tile (100 float4): 3 full warp rounds + 4-lane round.
__device__ __forceinline__ void stage_tile(const float4* __restrict__ logits_f4,
                                           int tile, uint32_t dst_base, int lane) {
    const float4* src = logits_f4 + (long long)tile * TILE_F4;
    #pragma unroll
    for (int i = 0; i < 3; i++)
        cp_async16(dst_base + (uint32_t)(i * 32 + lane) * 16u, src + i * 32 + lane);
    if (lane < 4)
        cp_async16(dst_base + (uint32_t)(96 + lane) * 16u, src + 96 + lane);
}

__global__ __launch_bounds__(BLOCK_THREADS, BLOCKS_PER_SM) void ece_fused_kernel(
    const float* __restrict__ logits,
    const int* __restrict__ labels,
    float* __restrict__ out,
    int n_rows, float inv_n)
{
    extern __shared__ float4 smem[];     // 4 warps * 200 f4 = 12800 B

    __shared__ float s_hist[WARPS_PER_BLOCK][75];
    __shared__ float s_fin[75];
    __shared__ int   s_last;

    int t    = threadIdx.x;
    int lane = t & 31;
    int wblk = t >> 5;

    for (int i = lane; i < 75; i += 32) s_hist[wblk][i] = 0.0f;
    __syncwarp();

    int gwarp   = blockIdx.x * WARPS_PER_BLOCK + wblk;
    int nwarps  = GRID_BLOCKS * WARPS_PER_BLOCK;
    int n_tiles = (n_rows + TILE_ROWS - 1) / TILE_ROWS;   // 500000/4 = 125000 exact

    const float4* logits_f4 = reinterpret_cast<const float4*>(logits);
    float4*  wbuf   = smem + wblk * BUF_F4;
    uint32_t wbuf_s = (uint32_t)__cvta_generic_to_shared(wbuf);

    int r = lane & 3;          // row within tile
    int q = lane >> 2;         // column eighth: f4 [q*3, q*3+3) (+1 extra for q==7)

    int tile = gwarp;
    int buf  = 0;
    if (tile < n_tiles) { stage_tile(logits_f4, tile, wbuf_s, lane); cp_commit(); }

    while (tile < n_tiles) {
        int next = tile + nwarps;
        if (next < n_tiles) {
            stage_tile(logits_f4, next, wbuf_s + (uint32_t)(buf ^ 1) * (TILE_F4 * 16u), lane);
            cp_commit();
            cp_wait<1>();
        } else {
            cp_wait<0>();
        }
        __syncwarp();

        // ---- compute: each lane handles 1/8 of a row; no argmax tracking ----
        const float4* rowp = wbuf + buf * TILE_F4 + r * ROW_F4;
        const float4* rp   = rowp + q * 3;

        float m   = -FLT_MAX;
        float sum = 0.0f;
        #pragma unroll
        for (int k = 0; k < 3; k++) {
            float4 v = rp[k];
            m = fmaxf(m, fmaxf(fmaxf(v.x, v.y), fmaxf(v.z, v.w)));
            sum += __expf(v.x);
            sum += __expf(v.y);
            sum += __expf(v.z);
            sum += __expf(v.w);
        }
        if (q == 7) {          // f4 index 24 (cols 96..99)
            float4 v = rp[3];
            m = fmaxf(m, fmaxf(fmaxf(v.x, v.y), fmaxf(v.z, v.w)));
            sum += __expf(v.x);
            sum += __expf(v.y);
            sum += __expf(v.z);
            sum += __expf(v.w);
        }

        // merge the 8 lane-slices of each row (reduce over q: xor 4, 8, 16)
        m   = fmaxf(m, __shfl_xor_sync(0xFFFFFFFFu, m, 4));
        sum +=         __shfl_xor_sync(0xFFFFFFFFu, sum, 4);
        m   = fmaxf(m, __shfl_xor_sync(0xFFFFFFFFu, m, 8));
        sum +=         __shfl_xor_sync(0xFFFFFFFFu, sum, 8);
        m   = fmaxf(m, __shfl_xor_sync(0xFFFFFFFFu, m, 16));
        sum +=         __shfl_xor_sync(0xFFFFFFFFu, sum, 16);

        int row = tile * TILE_ROWS + r;
        if (q == 0 && row < n_rows) {
            int   label   = __ldg(labels + row);
            float v_label = reinterpret_cast<const float*>(rowp)[label];
            float acc     = (v_label == m) ? 1.0f : 0.0f;   // argmax==label (ties ~never)
            float conf    = __fdividef(__expf(m), sum);     // max softmax prob
            int bin = (int)ceilf(conf * (float)N_BINS) - 1;
            bin = bin < 0 ? 0 : (bin > N_BINS - 1 ? N_BINS - 1 : bin);
            atomicAdd(&s_hist[wblk][bin],              1.0f);
            atomicAdd(&s_hist[wblk][bin + N_BINS],     conf);
            atomicAdd(&s_hist[wblk][bin + 2 * N_BINS], acc);
        }
        __syncwarp();   // all reads of buf done before it is re-staged

        tile = next;
        buf ^= 1;
    }

    // ---- block: reduce 4 warp histograms -> global atomics ----
    __syncthreads();
    if (t < 75) {
        float a = s_hist[0][t] + s_hist[1][t] + s_hist[2][t] + s_hist[3][t];
        atomicAdd(&g_accum[t], a);
    }
    __threadfence();
    __syncthreads();

    if (t == 0) {
        unsigned old = atomicAdd(&g_done, 1u);
        s_last = (old == (unsigned)(gridDim.x - 1)) ? 1 : 0;
    }
    __syncthreads();

    if (s_last) {
        if (t < 75) {
            volatile float* ga = g_accum;
            s_fin[t] = ga[t];
        }
        __syncthreads();
        if (t == 0) {
            float ece = 0.0f;
            #pragma unroll
            for (int i = 0; i < N_BINS; i++) {
                float c = s_fin[i];
                if (c > 0.0f) {
                    float avg_conf = s_fin[i + N_BINS] / c;
                    float avg_acc  = s_fin[i + 2 * N_BINS] / c;
                    ece += fabsf(avg_conf - avg_acc) * c * inv_n;
                }
            }
            out[0] = ece;
        }
        __syncthreads();
        if (t < 75) g_accum[t] = 0.0f;    // restore for next graph replay
        if (t == 0) g_done = 0u;
    }
}

extern "C" void kernel_launch(void* const* d_in, const int* in_sizes, int n_in,
                              void* d_out, int out_size) {
    const float* logits = (const float*)d_in[0];
    const int*   labels = (const int*)d_in[1];
    int n_rows = in_sizes[1];

    static bool attr_set = false;
    if (!attr_set) {
        cudaFuncSetAttribute(ece_fused_kernel,
                             cudaFuncAttributeMaxDynamicSharedMemorySize,
                             WARPS_PER_BLOCK * BUF_F4 * sizeof(float4));
        attr_set = true;
    }

    size_t smem_bytes = WARPS_PER_BLOCK * BUF_F4 * sizeof(float4);
    ece_fused_kernel<<<GRID_BLOCKS, BLOCK_THREADS, smem_bytes>>>(
        logits, labels, (float*)d_out, n_rows, 1.0f / (float)n_rows);
}

// round 10
// speedup vs baseline: 1.3194x; 1.3194x over previous
#include <cuda_runtime.h>
#include <cuda_bf16.h>
#include <float.h>
#include <stdint.h>

#define N_BINS 25
#define BLOCK_THREADS 128
#define WARPS_PER_BLOCK 4
#define BLOCKS_PER_SM 8
#define GRID_BLOCKS (148 * BLOCKS_PER_SM)      // 1184
#define ROW_F4 25                              // float4 per row
#define TILE_ROWS 8                            // rows per warp tile
#define TILE_F4 (TILE_ROWS * ROW_F4)           // 200 float4 = 3.2 KB
#define BUF_F4 (2 * TILE_F4)                   // double buffer = 6.4 KB / warp

__device__ float    g_accum[75];     // [0..24]=cnt [25..49]=conf [50..74]=acc
__device__ unsigned g_done;

__device__ __forceinline__ void cp_async16(uint32_t dst, const float4* src) {
    asm volatile("cp.async.cg.shared.global [%0], [%1], 16;\n" :: "r"(dst), "l"(src));
}
__device__ __forceinline__ void cp_commit() {
    asm volatile("cp.async.commit_group;\n" ::: "memory");
}
template <int N>
__device__ __forceinline__ void cp_wait() {
    asm volatile("cp.async.wait_group %0;\n" :: "n"(N) : "memory");
}

// Stage one 8-row tile (200 float4) from src: 6 full warp rounds + 8-lane round.
// src_lane must already include +lane.
__device__ __forceinline__ void stage_tile(const float4* src_lane, uint32_t dst_lane, int lane) {
    #pragma unroll
    for (int i = 0; i < 6; i++)
        cp_async16(dst_lane + (uint32_t)(i * 32) * 16u, src_lane + i * 32);
    if (lane < 8)
        cp_async16(dst_lane + (uint32_t)(192) * 16u, src_lane + 192);
}

__global__ __launch_bounds__(BLOCK_THREADS, BLOCKS_PER_SM) void ece_fused_kernel(
    const float* __restrict__ logits,
    const int* __restrict__ labels,
    float* __restrict__ out,
    int n_rows, float inv_n)
{
    extern __shared__ float4 smem[];     // 4 warps * 400 f4 = 25600 B

    __shared__ float s_hist[WARPS_PER_BLOCK][75];
    __shared__ float s_fin[75];
    __shared__ int   s_last;

    int t    = threadIdx.x;
    int lane = t & 31;
    int wblk = t >> 5;

    for (int i = lane; i < 75; i += 32) s_hist[wblk][i] = 0.0f;
    __syncwarp();

    int gwarp   = blockIdx.x * WARPS_PER_BLOCK + wblk;
    int nwarps  = GRID_BLOCKS * WARPS_PER_BLOCK;          // 4736
    int n_tiles = (n_rows + TILE_ROWS - 1) / TILE_ROWS;   // 62500 exact

    const float4* logits_f4 = reinterpret_cast<const float4*>(logits);
    float4*  wbuf   = smem + wblk * BUF_F4;
    uint32_t wbuf_s = (uint32_t)__cvta_generic_to_shared(wbuf);

    int r = lane & 7;          // row within tile
    int q = lane >> 3;         // column quarter: f4 [q*6, q*6+6) (+1 extra for q==3)

    // Precomputed per-lane pointers (loop body only selects/increments).
    const float4* src_lane = logits_f4 + (long long)gwarp * TILE_F4 + lane;
    const long long src_step = (long long)nwarps * TILE_F4;
    uint32_t dst0 = wbuf_s + (uint32_t)lane * 16u;
    uint32_t dst1 = dst0 + (uint32_t)TILE_F4 * 16u;
    const float4* rowp0 = wbuf + r * ROW_F4;
    const float4* rowp1 = rowp0 + TILE_F4;
    const int row_step = nwarps * TILE_ROWS;

    int tile = gwarp;
    int row  = gwarp * TILE_ROWS + r;
    int buf  = 0;
    if (tile < n_tiles) { stage_tile(src_lane, dst0, lane); cp_commit(); }

    while (tile < n_tiles) {
        int next = tile + nwarps;
        src_lane += src_step;                     // next tile's src
        if (next < n_tiles) {
            stage_tile(src_lane, buf ? dst0 : dst1, lane);
            cp_commit();
            cp_wait<1>();
        } else {
            cp_wait<0>();
        }
        __syncwarp();

        // Prefetch label early (only the lane that will use it).
        int label = 0;
        if (q == 0 && row < n_rows) label = __ldg(labels + row);

        // ---- compute: each lane handles a quarter-row; no argmax tracking ----
        const float4* rowp = buf ? rowp1 : rowp0;
        const float4* rp   = rowp + q * 6;

        float m   = -FLT_MAX;
        float sum = 0.0f;
        #pragma unroll
        for (int k = 0; k < 6; k++) {
            float4 v = rp[k];
            m = fmaxf(m, fmaxf(fmaxf(v.x, v.y), fmaxf(v.z, v.w)));
            sum += __expf(v.x);
            sum += __expf(v.y);
            sum += __expf(v.z);
            sum += __expf(v.w);
        }
        if (q == 3) {          // f4 index 24 (cols 96..99)
            float4 v = rp[6];
            m = fmaxf(m, fmaxf(fmaxf(v.x, v.y), fmaxf(v.z, v.w)));
            sum += __expf(v.x);
            sum += __expf(v.y);
            sum += __expf(v.z);
            sum += __expf(v.w);
        }

        // merge the 4 quarter-lanes of each row
        m   = fmaxf(m, __shfl_xor_sync(0xFFFFFFFFu, m, 8));
        sum +=         __shfl_xor_sync(0xFFFFFFFFu, sum, 8);
        m   = fmaxf(m, __shfl_xor_sync(0xFFFFFFFFu, m, 16));
        sum +=         __shfl_xor_sync(0xFFFFFFFFu, sum, 16);

        if (q == 0 && row < n_rows) {
            float v_label = reinterpret_cast<const float*>(rowp)[label];
            float acc     = (v_label == m) ? 1.0f : 0.0f;   // argmax==label (ties ~never)
            float conf    = __fdividef(__expf(m), sum);     // max softmax prob
            int bin = (int)ceilf(conf * (float)N_BINS) - 1;
            bin = bin < 0 ? 0 : (bin > N_BINS - 1 ? N_BINS - 1 : bin);
            atomicAdd(&s_hist[wblk][bin],              1.0f);
            atomicAdd(&s_hist[wblk][bin + N_BINS],     conf);
            atomicAdd(&s_hist[wblk][bin + 2 * N_BINS], acc);
        }
        __syncwarp();   // all reads of buf done before it is re-staged

        tile = next;
        row += row_step;
        buf ^= 1;
    }

    // ---- block: reduce 4 warp histograms -> global atomics ----
    __syncthreads();
    if (t < 75) {
        float a = s_hist[0][t] + s_hist[1][t] + s_hist[2][t] + s_hist[3][t];
        atomicAdd(&g_accum[t], a);
    }
    __threadfence();
    __syncthreads();

    if (t == 0) {
        unsigned old = atomicAdd(&g_done, 1u);
        s_last = (old == (unsigned)(gridDim.x - 1)) ? 1 : 0;
    }
    __syncthreads();

    if (s_last) {
        if (t < 75) {
            volatile float* ga = g_accum;
            s_fin[t] = ga[t];
        }
        __syncthreads();
        if (t == 0) {
            float ece = 0.0f;
            #pragma unroll
            for (int i = 0; i < N_BINS; i++) {
                float c = s_fin[i];
                if (c > 0.0f) {
                    float avg_conf = s_fin[i + N_BINS] / c;
                    float avg_acc  = s_fin[i + 2 * N_BINS] / c;
                    ece += fabsf(avg_conf - avg_acc) * c * inv_n;
                }
            }
            out[0] = ece;
        }
        __syncthreads();
        if (t < 75) g_accum[t] = 0.0f;    // restore for next graph replay
        if (t == 0) g_done = 0u;
    }
}

extern "C" void kernel_launch(void* const* d_in, const int* in_sizes, int n_in,
                              void* d_out, int out_size) {
    const float* logits = (const float*)d_in[0];
    const int*   labels = (const int*)d_in[1];
    int n_rows = in_sizes[1];

    static bool attr_set = false;
    if (!attr_set) {
        cudaFuncSetAttribute(ece_fused_kernel,
                             cudaFuncAttributeMaxDynamicSharedMemorySize,
                             WARPS_PER_BLOCK * BUF_F4 * sizeof(float4));
        attr_set = true;
    }

    size_t smem_bytes = WARPS_PER_BLOCK * BUF_F4 * sizeof(float4);
    ece_fused_kernel<<<GRID_BLOCKS, BLOCK_THREADS, smem_bytes>>>(
        logits, labels, (float*)d_out, n_rows, 1.0f / (float)n_rows);
}